// round 1
// baseline (speedup 1.0000x reference)
#include <cuda_runtime.h>
#include <cuda_bf16.h>

// Problem constants
// B=64, N=2048, CI=32, CO=64, K=3, D=16, RED=16
#define NN 2048
#define BB 64
#define CI 32
#define CO 64
#define DD 16

// Scratch layout (floats) inside one big device array
#define OFF_XP    0UL                       // [2048][2048]  Xp[m][b][ci]
#define OFF_Y1    4194304UL                 // [2048][2048]  L@Xp
#define OFF_G2    8388608UL                 // [2048][2048]  2*L@Y1 - Xp
#define OFF_U1    12582912UL                // [2048][2048]  P1@Xp
#define OFF_U2    16777216UL                // [2048][2048]  P2@Xp
#define OFF_WALL  20971520UL                // [2048][6144]  per-node weights
#define OFF_BALL  33554432UL                // [2048][64]
#define OFF_MCAT  33685504UL                // [96][64]
#define OFF_VV    33691648UL                // [3][64]
#define OFF_RS    33691840UL                // [2][2048]
#define OFF_A0    33695936UL                // [2048][64][64] lrelu(x_gconv0), layout [n][b][o]
#define OFF_A1    42084544UL                // [2048][64][64] lrelu(x_gconv1)
#define OFF_PART  50473152UL                // [16][4096]
#define OFF_MEAN  50538688UL                // [2][4096]
#define OFF_SV    50546880UL                // [2][64]
#define SCRATCH_FLOATS 50547008UL

__device__ float g_scratch[SCRATCH_FLOATS];

// ---------------------------------------------------------------------------
// Pack x[b][m][c] -> Xp[m][b][c]
__global__ void pack_x(const float* __restrict__ x, float* __restrict__ Xp) {
    int t = blockIdx.x * 256 + threadIdx.x;          // 64*2048*8 float4 slots
    int c4 = (t & 7) * 4;
    int m  = (t >> 3) & 2047;
    int b  = t >> 14;
    float4 v = *reinterpret_cast<const float4*>(x + ((size_t)b * NN + m) * CI + c4);
    *reinterpret_cast<float4*>(Xp + (size_t)m * (BB * CI) + b * CI + c4) = v;
}

// ---------------------------------------------------------------------------
// SGEMM: C[2048,2048] = A[2048,2048] @ B[2048,2048]   (MODE 1: C = 2*acc - D)
template <int MODE>
__global__ __launch_bounds__(256) void sgemm2048(
    const float* __restrict__ A, const float* __restrict__ B,
    float* __restrict__ C, const float* __restrict__ D)
{
    __shared__ float As[16][128];
    __shared__ float Bs[16][128];
    const int bm = blockIdx.y, bn = blockIdx.x;
    const int tid = threadIdx.x;
    const int tx = tid & 15, ty = tid >> 4;
    float acc[8][8];
    #pragma unroll
    for (int i = 0; i < 8; ++i)
        #pragma unroll
        for (int j = 0; j < 8; ++j) acc[i][j] = 0.f;

    const float* Ab = A + (size_t)bm * 128 * NN;
    const float* Bb = B + bn * 128;

    for (int kt = 0; kt < NN / 16; ++kt) {
        #pragma unroll
        for (int r = 0; r < 2; ++r) {
            int la = tid + r * 256;                  // 512 float4 for A tile
            int row = la >> 2, c4 = (la & 3) * 4;
            float4 a = *reinterpret_cast<const float4*>(Ab + (size_t)row * NN + kt * 16 + c4);
            As[c4 + 0][row] = a.x; As[c4 + 1][row] = a.y;
            As[c4 + 2][row] = a.z; As[c4 + 3][row] = a.w;
            int kr = la >> 5, n4 = (la & 31) * 4;    // 512 float4 for B tile
            *reinterpret_cast<float4*>(&Bs[kr][n4]) =
                *reinterpret_cast<const float4*>(Bb + (size_t)(kt * 16 + kr) * NN + n4);
        }
        __syncthreads();
        #pragma unroll
        for (int k = 0; k < 16; ++k) {
            float4 a0 = *reinterpret_cast<const float4*>(&As[k][ty * 8]);
            float4 a1 = *reinterpret_cast<const float4*>(&As[k][ty * 8 + 4]);
            float4 b0 = *reinterpret_cast<const float4*>(&Bs[k][tx * 8]);
            float4 b1 = *reinterpret_cast<const float4*>(&Bs[k][tx * 8 + 4]);
            float ar[8] = {a0.x, a0.y, a0.z, a0.w, a1.x, a1.y, a1.z, a1.w};
            float br[8] = {b0.x, b0.y, b0.z, b0.w, b1.x, b1.y, b1.z, b1.w};
            #pragma unroll
            for (int i = 0; i < 8; ++i)
                #pragma unroll
                for (int j = 0; j < 8; ++j)
                    acc[i][j] += ar[i] * br[j];
        }
        __syncthreads();
    }

    const int crow = bm * 128 + ty * 8;
    const int ccol = bn * 128 + tx * 8;
    #pragma unroll
    for (int i = 0; i < 8; ++i) {
        size_t idx = (size_t)(crow + i) * NN + ccol;
        float4 v0, v1;
        v0.x = acc[i][0]; v0.y = acc[i][1]; v0.z = acc[i][2]; v0.w = acc[i][3];
        v1.x = acc[i][4]; v1.y = acc[i][5]; v1.z = acc[i][6]; v1.w = acc[i][7];
        if (MODE == 1) {
            float4 d0 = *reinterpret_cast<const float4*>(D + idx);
            float4 d1 = *reinterpret_cast<const float4*>(D + idx + 4);
            v0.x = 2.f * v0.x - d0.x; v0.y = 2.f * v0.y - d0.y;
            v0.z = 2.f * v0.z - d0.z; v0.w = 2.f * v0.w - d0.w;
            v1.x = 2.f * v1.x - d1.x; v1.y = 2.f * v1.y - d1.y;
            v1.z = 2.f * v1.z - d1.z; v1.w = 2.f * v1.w - d1.w;
        }
        *reinterpret_cast<float4*>(C + idx) = v0;
        *reinterpret_cast<float4*>(C + idx + 4) = v1;
    }
}

// ---------------------------------------------------------------------------
// Wall[n][ki][o] = sum_d E[n][d] * Wp[d][ki][o]   (E:[2048,16], Wp:[16,6144])
__global__ __launch_bounds__(256) void wgen(
    const float* __restrict__ E, const float* __restrict__ Wp, float* __restrict__ Wall)
{
    __shared__ float Es[128][17];
    __shared__ float Bs[16][128];
    const int cb = blockIdx.x, nb = blockIdx.y;
    const int tid = threadIdx.x;
    #pragma unroll
    for (int r = 0; r < 2; ++r) {
        int la = tid + r * 256;
        int row = la >> 2, c4 = (la & 3) * 4;
        float4 v = *reinterpret_cast<const float4*>(E + (size_t)(nb * 128 + row) * DD + c4);
        Es[row][c4] = v.x; Es[row][c4 + 1] = v.y; Es[row][c4 + 2] = v.z; Es[row][c4 + 3] = v.w;
        int kr = la >> 5, n4 = (la & 31) * 4;
        *reinterpret_cast<float4*>(&Bs[kr][n4]) =
            *reinterpret_cast<const float4*>(Wp + (size_t)kr * 6144 + cb * 128 + n4);
    }
    __syncthreads();
    const int tx = tid & 15, ty = tid >> 4;
    float acc[8][8];
    #pragma unroll
    for (int i = 0; i < 8; ++i)
        #pragma unroll
        for (int j = 0; j < 8; ++j) acc[i][j] = 0.f;
    #pragma unroll
    for (int k = 0; k < 16; ++k) {
        float ar[8], br[8];
        #pragma unroll
        for (int i = 0; i < 8; ++i) ar[i] = Es[ty * 8 + i][k];
        #pragma unroll
        for (int j = 0; j < 8; ++j) br[j] = Bs[k][tx * 8 + j];
        #pragma unroll
        for (int i = 0; i < 8; ++i)
            #pragma unroll
            for (int j = 0; j < 8; ++j) acc[i][j] += ar[i] * br[j];
    }
    #pragma unroll
    for (int i = 0; i < 8; ++i) {
        size_t idx = (size_t)(nb * 128 + ty * 8 + i) * 6144 + cb * 128 + tx * 8;
        float4 v0, v1;
        v0.x = acc[i][0]; v0.y = acc[i][1]; v0.z = acc[i][2]; v0.w = acc[i][3];
        v1.x = acc[i][4]; v1.y = acc[i][5]; v1.z = acc[i][6]; v1.w = acc[i][7];
        *reinterpret_cast<float4*>(Wall + idx) = v0;
        *reinterpret_cast<float4*>(Wall + idx + 4) = v1;
    }
}

// Ball[n][o] = sum_d E[n][d] * Bp[d][o]
__global__ void bgen(const float* __restrict__ E, const float* __restrict__ Bp,
                     float* __restrict__ Ball)
{
    int t = blockIdx.x * 256 + threadIdx.x;          // 2048*64
    int n = t >> 6, o = t & 63;
    float s = 0.f;
    #pragma unroll
    for (int d = 0; d < DD; ++d) s += E[n * DD + d] * Bp[d * CO + o];
    Ball[t] = s;
}

// Mcat[k*32+i][o] = sum_j init_w[i][j]*gconv_w[k*64+j][o];  vv[k][o] = sum_j init_b[j]*gconv_w[k*64+j][o]
__global__ void prestat(const float* __restrict__ iw, const float* __restrict__ ib,
                        const float* __restrict__ gw, float* __restrict__ Mcat,
                        float* __restrict__ vv)
{
    int tid = threadIdx.x;
    for (int idx = tid; idx < 96 * 64; idx += 256) {
        int ki = idx >> 6, o = idx & 63;
        int k = ki >> 5, i = ki & 31;
        float s = 0.f;
        #pragma unroll 8
        for (int j = 0; j < 64; ++j) s += iw[i * 64 + j] * gw[(k * 64 + j) * 64 + o];
        Mcat[idx] = s;
    }
    for (int idx = tid; idx < 192; idx += 256) {
        int k = idx >> 6, o = idx & 63;
        float s = 0.f;
        #pragma unroll 8
        for (int j = 0; j < 64; ++j) s += ib[j] * gw[(k * 64 + j) * 64 + o];
        vv[idx] = s;
    }
}

// rs[0][n] = rowsum(cheb[1], n); rs[1][n] = rowsum(cheb[2], n)
__global__ void rowsums(const float* __restrict__ cheb, float* __restrict__ rs) {
    __shared__ float sm[2][8];
    int n = blockIdx.x, tid = threadIdx.x;
    const float* p1 = cheb + 4194304UL + (size_t)n * NN;
    const float* p2 = cheb + 8388608UL + (size_t)n * NN;
    float s1 = 0.f, s2 = 0.f;
    for (int m = tid; m < NN; m += 256) { s1 += p1[m]; s2 += p2[m]; }
    #pragma unroll
    for (int off = 16; off; off >>= 1) {
        s1 += __shfl_down_sync(0xFFFFFFFFu, s1, off);
        s2 += __shfl_down_sync(0xFFFFFFFFu, s2, off);
    }
    if ((tid & 31) == 0) { sm[0][tid >> 5] = s1; sm[1][tid >> 5] = s2; }
    __syncthreads();
    if (tid == 0) {
        float a = 0.f, b = 0.f;
        #pragma unroll
        for (int w = 0; w < 8; ++w) { a += sm[0][w]; b += sm[1][w]; }
        rs[n] = a; rs[NN + n] = b;
    }
}

// ---------------------------------------------------------------------------
// Per-node combine: out[n][b][o] = lrelu( sum_ki xg[n][b][ki]*W[ki][o] + bias )
// MODE 0 (learned): W = Wall+n*6144, bias = Ball[n][o]
// MODE 1 (static):  W = Mcat,        bias = vv0[o]+rs1[n]*vv1[o]+rs2[n]*vv2[o]+gb[o]
template <int MODE>
__global__ __launch_bounds__(256) void combine(
    const float* __restrict__ S0, const float* __restrict__ S1, const float* __restrict__ S2,
    const float* __restrict__ W, const float* __restrict__ bias,
    const float* __restrict__ gb, const float* __restrict__ rs,
    float* __restrict__ out)
{
    __shared__ float xg[64][97];
    __shared__ float bv[64];
    const int n = blockIdx.x, tid = threadIdx.x;

    for (int idx = tid; idx < 2048; idx += 256) {
        int b = idx >> 5, i = idx & 31;
        xg[b][i]      = S0[(size_t)n * 2048 + idx];
        xg[b][32 + i] = S1[(size_t)n * 2048 + idx];
        xg[b][64 + i] = S2[(size_t)n * 2048 + idx];
    }
    if (tid < 64) {
        if (MODE == 0) bv[tid] = bias[(size_t)n * 64 + tid];
        else bv[tid] = bias[tid] + rs[n] * bias[64 + tid] + rs[NN + n] * bias[128 + tid] + gb[tid];
    }
    __syncthreads();

    const float* Wn = (MODE == 0) ? (W + (size_t)n * 6144) : W;
    const int b0 = (tid >> 4) * 4;
    const int o0 = (tid & 15) * 4;
    float acc[4][4];
    #pragma unroll
    for (int i = 0; i < 4; ++i)
        #pragma unroll
        for (int j = 0; j < 4; ++j) acc[i][j] = 0.f;

    #pragma unroll 4
    for (int ki = 0; ki < 96; ++ki) {
        float4 w = *reinterpret_cast<const float4*>(Wn + ki * 64 + o0);
        float a0 = xg[b0][ki], a1 = xg[b0 + 1][ki], a2 = xg[b0 + 2][ki], a3 = xg[b0 + 3][ki];
        acc[0][0] += a0 * w.x; acc[0][1] += a0 * w.y; acc[0][2] += a0 * w.z; acc[0][3] += a0 * w.w;
        acc[1][0] += a1 * w.x; acc[1][1] += a1 * w.y; acc[1][2] += a1 * w.z; acc[1][3] += a1 * w.w;
        acc[2][0] += a2 * w.x; acc[2][1] += a2 * w.y; acc[2][2] += a2 * w.z; acc[2][3] += a2 * w.w;
        acc[3][0] += a3 * w.x; acc[3][1] += a3 * w.y; acc[3][2] += a3 * w.z; acc[3][3] += a3 * w.w;
    }
    #pragma unroll
    for (int bi = 0; bi < 4; ++bi) {
        float4 v;
        float t0 = acc[bi][0] + bv[o0 + 0];
        float t1 = acc[bi][1] + bv[o0 + 1];
        float t2 = acc[bi][2] + bv[o0 + 2];
        float t3 = acc[bi][3] + bv[o0 + 3];
        v.x = t0 >= 0.f ? t0 : 0.01f * t0;
        v.y = t1 >= 0.f ? t1 : 0.01f * t1;
        v.z = t2 >= 0.f ? t2 : 0.01f * t2;
        v.w = t3 >= 0.f ? t3 : 0.01f * t3;
        *reinterpret_cast<float4*>(out + (size_t)n * 4096 + (b0 + bi) * 64 + o0) = v;
    }
}

// ---------------------------------------------------------------------------
// Deterministic column sums over n (for SelfAtt mean)
__global__ void colsum(const float* __restrict__ src, float* __restrict__ part) {
    int c = blockIdx.x * 256 + threadIdx.x;           // 16 blocks * 256 = 4096 cols
    int n0 = blockIdx.y * 128;
    float s = 0.f;
    #pragma unroll 4
    for (int n = 0; n < 128; ++n) s += src[(size_t)(n0 + n) * 4096 + c];
    part[(size_t)blockIdx.y * 4096 + c] = s;
}
__global__ void colsum_fin(const float* __restrict__ part, float* __restrict__ mean) {
    int c = blockIdx.x * 256 + threadIdx.x;
    float s = 0.f;
    #pragma unroll
    for (int p = 0; p < 16; ++p) s += part[(size_t)p * 4096 + c];
    mean[c] = s * (1.0f / 2048.0f);
}

// SelfAtt MLPs -> per-batch scalars s0,s1
__global__ void selfatt(const float* __restrict__ w11, const float* __restrict__ w12,
                        const float* __restrict__ w21, const float* __restrict__ w22,
                        const float* __restrict__ mean, float* __restrict__ sv)
{
    int b = threadIdx.x;
    if (b >= 64) return;
    {
        float h[4] = {0.f, 0.f, 0.f, 0.f};
        for (int c = 0; c < 64; ++c) {
            float m = mean[b * 64 + c];
            #pragma unroll
            for (int r = 0; r < 4; ++r) h[r] += m * w11[c * 4 + r];
        }
        float s = 0.f;
        #pragma unroll
        for (int r = 0; r < 4; ++r) s += fmaxf(h[r], 0.f) * w12[r];
        sv[b] = fminf(fmaxf(s * (1.0f / 6.0f) + 0.5f, 0.f), 1.f);
    }
    {
        float h[4] = {0.f, 0.f, 0.f, 0.f};
        for (int c = 0; c < 64; ++c) {
            float m = mean[4096 + b * 64 + c];
            #pragma unroll
            for (int r = 0; r < 4; ++r) h[r] += m * w21[c * 4 + r];
        }
        float s = 0.f;
        #pragma unroll
        for (int r = 0; r < 4; ++r) s += fmaxf(h[r], 0.f) * w22[r];
        sv[64 + b] = fminf(fmaxf(s * (1.0f / 6.0f) + 0.5f, 0.f), 1.f);
    }
}

// out[b][n][o] = a0[n][b][o]*s0[b] + a1[n][b][o]*s1[b]
__global__ void finalize(const float* __restrict__ a0, const float* __restrict__ a1,
                         const float* __restrict__ sv, float* __restrict__ out)
{
    int t = blockIdx.x * 256 + threadIdx.x;           // 2,097,152 float4
    int b = (t >> 4) & 63;
    int n = t >> 10;
    int o4 = (t & 15) << 2;
    float4 v0 = *(reinterpret_cast<const float4*>(a0) + t);
    float4 v1 = *(reinterpret_cast<const float4*>(a1) + t);
    float f0 = sv[b], f1 = sv[64 + b];
    float4 r;
    r.x = v0.x * f0 + v1.x * f1;
    r.y = v0.y * f0 + v1.y * f1;
    r.z = v0.z * f0 + v1.z * f1;
    r.w = v0.w * f0 + v1.w * f1;
    *reinterpret_cast<float4*>(out + ((size_t)b * NN + n) * 64 + o4) = r;
}

// ---------------------------------------------------------------------------
extern "C" void kernel_launch(void* const* d_in, const int* in_sizes, int n_in,
                              void* d_out, int out_size)
{
    (void)in_sizes; (void)n_in; (void)out_size;
    const float* x    = (const float*)d_in[0];
    const float* E    = (const float*)d_in[1];
    const float* L    = (const float*)d_in[2];
    const float* cheb = (const float*)d_in[3];
    const float* Wp   = (const float*)d_in[4];
    const float* Bp   = (const float*)d_in[5];
    const float* iw   = (const float*)d_in[6];
    const float* ib   = (const float*)d_in[7];
    const float* gw   = (const float*)d_in[8];
    const float* gb   = (const float*)d_in[9];
    const float* w11  = (const float*)d_in[10];
    const float* w12  = (const float*)d_in[11];
    const float* w21  = (const float*)d_in[12];
    const float* w22  = (const float*)d_in[13];
    float* out = (float*)d_out;

    float* S = nullptr;
    cudaGetSymbolAddress((void**)&S, g_scratch);

    pack_x<<<4096, 256>>>(x, S + OFF_XP);

    dim3 gg(16, 16);
    sgemm2048<0><<<gg, 256>>>(L, S + OFF_XP, S + OFF_Y1, nullptr);
    sgemm2048<1><<<gg, 256>>>(L, S + OFF_Y1, S + OFF_G2, S + OFF_XP);
    sgemm2048<0><<<gg, 256>>>(cheb + 4194304UL, S + OFF_XP, S + OFF_U1, nullptr);
    sgemm2048<0><<<gg, 256>>>(cheb + 8388608UL, S + OFF_XP, S + OFF_U2, nullptr);

    wgen<<<dim3(48, 16), 256>>>(E, Wp, S + OFF_WALL);
    bgen<<<512, 256>>>(E, Bp, S + OFF_BALL);
    prestat<<<1, 256>>>(iw, ib, gw, S + OFF_MCAT, S + OFF_VV);
    rowsums<<<2048, 256>>>(cheb, S + OFF_RS);

    combine<0><<<2048, 256>>>(S + OFF_XP, S + OFF_Y1, S + OFF_G2,
                              S + OFF_WALL, S + OFF_BALL, nullptr, nullptr, S + OFF_A0);
    combine<1><<<2048, 256>>>(S + OFF_XP, S + OFF_U1, S + OFF_U2,
                              S + OFF_MCAT, S + OFF_VV, gb, S + OFF_RS, S + OFF_A1);

    colsum<<<dim3(16, 16), 256>>>(S + OFF_A0, S + OFF_PART);
    colsum_fin<<<16, 256>>>(S + OFF_PART, S + OFF_MEAN);
    colsum<<<dim3(16, 16), 256>>>(S + OFF_A1, S + OFF_PART);
    colsum_fin<<<16, 256>>>(S + OFF_PART, S + OFF_MEAN + 4096);

    selfatt<<<1, 64>>>(w11, w12, w21, w22, S + OFF_MEAN, S + OFF_SV);

    finalize<<<8192, 256>>>(S + OFF_A0, S + OFF_A1, S + OFF_SV, out);
}

// round 3
// speedup vs baseline: 2.2733x; 2.2733x over previous
#include <cuda_runtime.h>
#include <cuda_bf16.h>
#include <cstdint>

// Problem constants: B=64, N=2048, CI=32, CO=64, K=3, D=16, RED=16
#define NN 2048
#define BB 64
#define CI 32
#define CO 64
#define DD 16

// ---------------------------------------------------------------------------
// fp32 scratch
#define OFF_XP    0UL                       // [2048][2048]  Xp[m][j]
#define OFF_Y1    4194304UL                 // [2048][2048]
#define OFF_G2    8388608UL
#define OFF_U1    12582912UL
#define OFF_U2    16777216UL
#define OFF_WALL  20971520UL                // [2048][6144]
#define OFF_BALL  33554432UL                // [2048][64]
#define OFF_MCAT  33685504UL                // [96][64]
#define OFF_VV    33691648UL                // [3][64]
#define OFF_RS    33691840UL                // [2][2048]
#define OFF_A0    33695936UL                // [2048][64][64]
#define OFF_A1    42084544UL
#define OFF_PART  50473152UL                // [16][4096]
#define OFF_MEAN  50538688UL                // [2][4096]
#define OFF_SV    50546880UL                // [2][64]
#define SCRATCH_FLOATS 50547008UL

__device__ float g_scratch[SCRATCH_FLOATS];

// bf16 fragment-layout operand arrays (each 2048x2048 = 4194304 bf16 = 8MB)
#define BF_LH   0UL
#define BF_LL   4194304UL
#define BF_C1H  8388608UL
#define BF_C1L  12582912UL
#define BF_C2H  16777216UL
#define BF_C2L  20971520UL
#define BF_XTH  25165824UL
#define BF_XTL  29360128UL
#define BF_YTH  33554432UL
#define BF_YTL  37748736UL
#define BF_TOTAL 41943040UL

__device__ __align__(1024) __nv_bfloat16 g_bf[BF_TOTAL];

// ---------------------------------------------------------------------------
__device__ __forceinline__ uint32_t smem_u32(const void* p) {
    uint32_t a;
    asm("{ .reg .u64 t; cvta.to.shared.u64 t, %1; cvt.u32.u64 %0, t; }" : "=r"(a) : "l"(p));
    return a;
}
__device__ __forceinline__ void cp16(uint32_t s, const void* g) {
    asm volatile("cp.async.cg.shared.global [%0], [%1], 16;" :: "r"(s), "l"(g));
}
__device__ __forceinline__ uint4 lds128(uint32_t a) {
    uint4 v;
    asm volatile("ld.shared.v4.b32 {%0,%1,%2,%3}, [%4];"
                 : "=r"(v.x), "=r"(v.y), "=r"(v.z), "=r"(v.w) : "r"(a));
    return v;
}
__device__ __forceinline__ void mma16816(float* d, const uint4& a, uint32_t b0, uint32_t b1) {
    asm volatile(
        "mma.sync.aligned.m16n8k16.row.col.f32.bf16.bf16.f32 "
        "{%0,%1,%2,%3},{%4,%5,%6,%7},{%8,%9},{%0,%1,%2,%3};"
        : "+f"(d[0]), "+f"(d[1]), "+f"(d[2]), "+f"(d[3])
        : "r"(a.x), "r"(a.y), "r"(a.z), "r"(a.w), "r"(b0), "r"(b1));
}
__device__ __forceinline__ uint32_t pack_bf2(float v0, float v1) {
    __nv_bfloat162 p;
    p.x = __float2bfloat16(v0);
    p.y = __float2bfloat16(v1);
    return *reinterpret_cast<uint32_t*>(&p);
}

// ---------------------------------------------------------------------------
// Pack x[b][m][c] -> Xp[m][b*32+c]  (fp32 natural)
__global__ void pack_x(const float* __restrict__ x, float* __restrict__ Xp) {
    int t = blockIdx.x * 256 + threadIdx.x;
    int c4 = (t & 7) * 4;
    int m  = (t >> 3) & 2047;
    int b  = t >> 14;
    float4 v = *reinterpret_cast<const float4*>(x + ((size_t)b * NN + m) * CI + c4);
    *reinterpret_cast<float4*>(Xp + (size_t)m * (BB * CI) + b * CI + c4) = v;
}

// ---------------------------------------------------------------------------
// A-fragment conversion: natural fp32 [row m][col k] -> Ah/Al frag arrays.
// Frag array layout: [mt(=m>>4) 128][kt(=k>>4) 128][lane 32][16B], where for
// element (m,k): g=m&7, hi8=(m>>3)&1, t=(k&7)>>1, klo=k&1, khi=(k>>3)&1,
// lane=g*4+t, word=khi*2+hi8, half=klo.
__global__ __launch_bounds__(256) void convA_frag(const float* __restrict__ src,
                                                  uint4* __restrict__ Ah,
                                                  uint4* __restrict__ Al)
{
    __shared__ float sm[64][65];
    const int bx = blockIdx.x, by = blockIdx.y;   // k-region, m-region
    const int tid = threadIdx.x;
    const float* s0 = src + (size_t)(by * 64) * 2048 + bx * 64;
    #pragma unroll
    for (int i = 0; i < 4; ++i) {
        int idx = tid + i * 256;
        int r = idx >> 4, c4 = (idx & 15) * 4;
        float4 v = *reinterpret_cast<const float4*>(s0 + (size_t)r * 2048 + c4);
        sm[r][c4] = v.x; sm[r][c4 + 1] = v.y; sm[r][c4 + 2] = v.z; sm[r][c4 + 3] = v.w;
    }
    __syncthreads();
    const int w = tid >> 5, lane = tid & 31, g = lane >> 2, t = lane & 3;
    #pragma unroll
    for (int rep = 0; rep < 2; ++rep) {
        int id = w * 2 + rep;
        int mt_l = id >> 2, kt_l = id & 3;
        uint32_t hw[4], lw[4];
        #pragma unroll
        for (int wd = 0; wd < 4; ++wd) {
            int khi = wd >> 1, hi8 = wd & 1;
            int m = mt_l * 16 + hi8 * 8 + g;
            int k = kt_l * 16 + khi * 8 + t * 2;
            float v0 = sm[m][k], v1 = sm[m][k + 1];
            __nv_bfloat16 h0 = __float2bfloat16(v0), h1 = __float2bfloat16(v1);
            hw[wd] = pack_bf2(v0, v1);
            lw[wd] = pack_bf2(v0 - __bfloat162float(h0), v1 - __bfloat162float(h1));
        }
        size_t fi = (((size_t)by * 4 + mt_l) * 128 + (bx * 4 + kt_l)) * 32 + lane;
        Ah[fi] = make_uint4(hw[0], hw[1], hw[2], hw[3]);
        Al[fi] = make_uint4(lw[0], lw[1], lw[2], lw[3]);
    }
}

// B-fragment conversion: natural fp32 src[m][j] (K=m, B-row=j) -> Bh/Bl frags.
// Frag layout: [ntp(=j>>4) 128][kt(=m>>4) 128][lane 32][16B]; element (j,m):
// g=j&7, nt_odd=(j>>3)&1, t=(m&7)>>1, klo=m&1, khi=(m>>3)&1,
// lane=g*4+t, word=nt_odd*2+khi, half=klo.
__global__ __launch_bounds__(256) void convB_frag(const float* __restrict__ src,
                                                  uint4* __restrict__ Bh,
                                                  uint4* __restrict__ Bl)
{
    __shared__ float sm[64][65];
    const int bx = blockIdx.x, by = blockIdx.y;   // j-region, m-region
    const int tid = threadIdx.x;
    const float* s0 = src + (size_t)(by * 64) * 2048 + bx * 64;
    #pragma unroll
    for (int i = 0; i < 4; ++i) {
        int idx = tid + i * 256;
        int r = idx >> 4, c4 = (idx & 15) * 4;
        float4 v = *reinterpret_cast<const float4*>(s0 + (size_t)r * 2048 + c4);
        sm[r][c4] = v.x; sm[r][c4 + 1] = v.y; sm[r][c4 + 2] = v.z; sm[r][c4 + 3] = v.w;
    }
    __syncthreads();
    const int w = tid >> 5, lane = tid & 31, g = lane >> 2, t = lane & 3;
    #pragma unroll
    for (int rep = 0; rep < 2; ++rep) {
        int id = w * 2 + rep;
        int ntp_l = id >> 2, kt_l = id & 3;
        uint32_t hw[4], lw[4];
        #pragma unroll
        for (int wd = 0; wd < 4; ++wd) {
            int nt_odd = wd >> 1, khi = wd & 1;
            int j = ntp_l * 16 + nt_odd * 8 + g;
            int m = kt_l * 16 + khi * 8 + t * 2;
            float v0 = sm[m][j], v1 = sm[m + 1][j];
            __nv_bfloat16 h0 = __float2bfloat16(v0), h1 = __float2bfloat16(v1);
            hw[wd] = pack_bf2(v0, v1);
            lw[wd] = pack_bf2(v0 - __bfloat162float(h0), v1 - __bfloat162float(h1));
        }
        size_t fi = (((size_t)bx * 4 + ntp_l) * 128 + (by * 4 + kt_l)) * 32 + lane;
        Bh[fi] = make_uint4(hw[0], hw[1], hw[2], hw[3]);
        Bl[fi] = make_uint4(lw[0], lw[1], lw[2], lw[3]);
    }
}

// B-fragment conversion directly from x[b][m][ci]: B-row j = b*32+ci, K = m.
__global__ __launch_bounds__(256) void convX_frag(const float* __restrict__ x,
                                                  uint4* __restrict__ Bh,
                                                  uint4* __restrict__ Bl)
{
    __shared__ float sm[64][65];
    const int bx = blockIdx.x, by = blockIdx.y;   // j-region (2 b's), m-region
    const int tid = threadIdx.x;
    for (int i = 0; i < 16; ++i) {
        int idx = tid + i * 256;                   // 4096 elems
        int b_l = idx >> 11, m_l = (idx >> 5) & 63, ci = idx & 31;
        sm[m_l][b_l * 32 + ci] =
            x[((size_t)(bx * 2 + b_l) * 2048 + by * 64 + m_l) * 32 + ci];
    }
    __syncthreads();
    const int w = tid >> 5, lane = tid & 31, g = lane >> 2, t = lane & 3;
    #pragma unroll
    for (int rep = 0; rep < 2; ++rep) {
        int id = w * 2 + rep;
        int ntp_l = id >> 2, kt_l = id & 3;
        uint32_t hw[4], lw[4];
        #pragma unroll
        for (int wd = 0; wd < 4; ++wd) {
            int nt_odd = wd >> 1, khi = wd & 1;
            int j = ntp_l * 16 + nt_odd * 8 + g;
            int m = kt_l * 16 + khi * 8 + t * 2;
            float v0 = sm[m][j], v1 = sm[m + 1][j];
            __nv_bfloat16 h0 = __float2bfloat16(v0), h1 = __float2bfloat16(v1);
            hw[wd] = pack_bf2(v0, v1);
            lw[wd] = pack_bf2(v0 - __bfloat162float(h0), v1 - __bfloat162float(h1));
        }
        size_t fi = (((size_t)bx * 4 + ntp_l) * 128 + (by * 4 + kt_l)) * 32 + lane;
        Bh[fi] = make_uint4(hw[0], hw[1], hw[2], hw[3]);
        Bl[fi] = make_uint4(lw[0], lw[1], lw[2], lw[3]);
    }
}

// ---------------------------------------------------------------------------
// bf16-split tensor-core GEMM via mma.sync: C[2048,2048] = A @ Bt^T (fp32 out)
// acc = Ah*Bh + Ah*Bl + Al*Bh.  CTA 128(M)x256(N), warp 64x64, BK=32, 3-stage.
// MODE 0: C = acc.  MODE 2: C = 2*acc - Xp.
#define ST_BYTES 49152

template <int MODE>
__global__ __launch_bounds__(256, 1) void gemm_mma(
    const uint4* __restrict__ Ah, const uint4* __restrict__ Al,
    const uint4* __restrict__ Bh, const uint4* __restrict__ Bl,
    float* __restrict__ C, const float* __restrict__ Xp)
{
    extern __shared__ char smem[];
    const int tid = threadIdx.x, lane = tid & 31, wid = tid >> 5;
    const int wm = wid >> 2, wn = wid & 3;
    const int g = lane >> 2, t = lane & 3;
    const int bn = blockIdx.x, bm = blockIdx.y;
    const uint32_t sb = smem_u32(smem);

    float acc[4][8][4];
    #pragma unroll
    for (int i = 0; i < 4; ++i)
        #pragma unroll
        for (int j = 0; j < 8; ++j)
            #pragma unroll
            for (int q = 0; q < 4; ++q) acc[i][j][q] = 0.f;

    auto issue = [&](int c) {
        uint32_t SB = sb + (c % 3) * ST_BYTES;
        #pragma unroll
        for (int r2 = 0; r2 < 2; ++r2) {
            int q = tid + r2 * 256;
            int u = q >> 5, ln = q & 31;
            size_t gi = (((size_t)bm * 8 + (u >> 1)) * 128 + (c * 2 + (u & 1))) * 32 + ln;
            cp16(SB + q * 16, Ah + gi);
            cp16(SB + 8192 + q * 16, Al + gi);
        }
        #pragma unroll
        for (int r2 = 0; r2 < 4; ++r2) {
            int q = tid + r2 * 256;
            int u = q >> 5, ln = q & 31;
            size_t gi = (((size_t)bn * 16 + (u >> 1)) * 128 + (c * 2 + (u & 1))) * 32 + ln;
            cp16(SB + 16384 + q * 16, Bh + gi);
            cp16(SB + 32768 + q * 16, Bl + gi);
        }
    };

    issue(0);
    asm volatile("cp.async.commit_group;" ::: "memory");
    issue(1);
    asm volatile("cp.async.commit_group;" ::: "memory");

    for (int c = 0; c < 64; ++c) {
        if (c + 2 < 64) issue(c + 2);
        asm volatile("cp.async.commit_group;" ::: "memory");
        asm volatile("cp.async.wait_group 2;" ::: "memory");
        __syncthreads();
        const uint32_t SB = sb + (c % 3) * ST_BYTES;
        #pragma unroll
        for (int ktl = 0; ktl < 2; ++ktl) {
            uint4 ah[4], bh[4];
            #pragma unroll
            for (int mt = 0; mt < 4; ++mt)
                ah[mt] = lds128(SB + ((wm * 4 + mt) * 2 + ktl) * 512 + lane * 16);
            #pragma unroll
            for (int np = 0; np < 4; ++np)
                bh[np] = lds128(SB + 16384 + ((wn * 4 + np) * 2 + ktl) * 512 + lane * 16);
            #pragma unroll
            for (int mt = 0; mt < 4; ++mt)
                #pragma unroll
                for (int np = 0; np < 4; ++np) {
                    mma16816(acc[mt][np * 2],     ah[mt], bh[np].x, bh[np].y);
                    mma16816(acc[mt][np * 2 + 1], ah[mt], bh[np].z, bh[np].w);
                }
            uint4 bl[4];
            #pragma unroll
            for (int np = 0; np < 4; ++np)
                bl[np] = lds128(SB + 32768 + ((wn * 4 + np) * 2 + ktl) * 512 + lane * 16);
            #pragma unroll
            for (int mt = 0; mt < 4; ++mt)
                #pragma unroll
                for (int np = 0; np < 4; ++np) {
                    mma16816(acc[mt][np * 2],     ah[mt], bl[np].x, bl[np].y);
                    mma16816(acc[mt][np * 2 + 1], ah[mt], bl[np].z, bl[np].w);
                }
            uint4 al[4];
            #pragma unroll
            for (int mt = 0; mt < 4; ++mt)
                al[mt] = lds128(SB + 8192 + ((wm * 4 + mt) * 2 + ktl) * 512 + lane * 16);
            #pragma unroll
            for (int mt = 0; mt < 4; ++mt)
                #pragma unroll
                for (int np = 0; np < 4; ++np) {
                    mma16816(acc[mt][np * 2],     al[mt], bh[np].x, bh[np].y);
                    mma16816(acc[mt][np * 2 + 1], al[mt], bh[np].z, bh[np].w);
                }
        }
        __syncthreads();
    }

    // epilogue
    const int row0 = bm * 128 + wm * 64;
    const int col0 = bn * 256 + wn * 64;
    #pragma unroll
    for (int mt = 0; mt < 4; ++mt)
        #pragma unroll
        for (int nt = 0; nt < 8; ++nt) {
            int r = row0 + mt * 16 + g;
            int cc = col0 + nt * 8 + t * 2;
            float* a = acc[mt][nt];
            float v0 = a[0], v1 = a[1], v2 = a[2], v3 = a[3];
            size_t i0 = (size_t)r * 2048 + cc;
            size_t i1 = (size_t)(r + 8) * 2048 + cc;
            if (MODE == 2) {
                float2 x0 = *reinterpret_cast<const float2*>(Xp + i0);
                float2 x1 = *reinterpret_cast<const float2*>(Xp + i1);
                v0 = 2.f * v0 - x0.x; v1 = 2.f * v1 - x0.y;
                v2 = 2.f * v2 - x1.x; v3 = 2.f * v3 - x1.y;
            }
            *reinterpret_cast<float2*>(C + i0) = make_float2(v0, v1);
            *reinterpret_cast<float2*>(C + i1) = make_float2(v2, v3);
        }
}

// ---------------------------------------------------------------------------
// Wall[n][ki][o] = sum_d E[n][d] * Wp[d][ki][o]
__global__ __launch_bounds__(256) void wgen(
    const float* __restrict__ E, const float* __restrict__ Wp, float* __restrict__ Wall)
{
    __shared__ float Es[128][17];
    __shared__ float Bs[16][128];
    const int cb = blockIdx.x, nb = blockIdx.y;
    const int tid = threadIdx.x;
    #pragma unroll
    for (int r = 0; r < 2; ++r) {
        int la = tid + r * 256;
        int row = la >> 2, c4 = (la & 3) * 4;
        float4 v = *reinterpret_cast<const float4*>(E + (size_t)(nb * 128 + row) * DD + c4);
        Es[row][c4] = v.x; Es[row][c4 + 1] = v.y; Es[row][c4 + 2] = v.z; Es[row][c4 + 3] = v.w;
        int kr = la >> 5, n4 = (la & 31) * 4;
        *reinterpret_cast<float4*>(&Bs[kr][n4]) =
            *reinterpret_cast<const float4*>(Wp + (size_t)kr * 6144 + cb * 128 + n4);
    }
    __syncthreads();
    const int tx = tid & 15, ty = tid >> 4;
    float acc[8][8];
    #pragma unroll
    for (int i = 0; i < 8; ++i)
        #pragma unroll
        for (int j = 0; j < 8; ++j) acc[i][j] = 0.f;
    #pragma unroll
    for (int k = 0; k < 16; ++k) {
        float ar[8], br[8];
        #pragma unroll
        for (int i = 0; i < 8; ++i) ar[i] = Es[ty * 8 + i][k];
        #pragma unroll
        for (int j = 0; j < 8; ++j) br[j] = Bs[k][tx * 8 + j];
        #pragma unroll
        for (int i = 0; i < 8; ++i)
            #pragma unroll
            for (int j = 0; j < 8; ++j) acc[i][j] += ar[i] * br[j];
    }
    #pragma unroll
    for (int i = 0; i < 8; ++i) {
        size_t idx = (size_t)(nb * 128 + ty * 8 + i) * 6144 + cb * 128 + tx * 8;
        float4 v0, v1;
        v0.x = acc[i][0]; v0.y = acc[i][1]; v0.z = acc[i][2]; v0.w = acc[i][3];
        v1.x = acc[i][4]; v1.y = acc[i][5]; v1.z = acc[i][6]; v1.w = acc[i][7];
        *reinterpret_cast<float4*>(Wall + idx) = v0;
        *reinterpret_cast<float4*>(Wall + idx + 4) = v1;
    }
}

__global__ void bgen(const float* __restrict__ E, const float* __restrict__ Bp,
                     float* __restrict__ Ball)
{
    int t = blockIdx.x * 256 + threadIdx.x;
    int n = t >> 6, o = t & 63;
    float s = 0.f;
    #pragma unroll
    for (int d = 0; d < DD; ++d) s += E[n * DD + d] * Bp[d * CO + o];
    Ball[t] = s;
}

__global__ void prestat(const float* __restrict__ iw, const float* __restrict__ ib,
                        const float* __restrict__ gw, float* __restrict__ Mcat,
                        float* __restrict__ vv)
{
    int tid = threadIdx.x;
    for (int idx = tid; idx < 96 * 64; idx += 256) {
        int ki = idx >> 6, o = idx & 63;
        int k = ki >> 5, i = ki & 31;
        float s = 0.f;
        #pragma unroll 8
        for (int j = 0; j < 64; ++j) s += iw[i * 64 + j] * gw[(k * 64 + j) * 64 + o];
        Mcat[idx] = s;
    }
    for (int idx = tid; idx < 192; idx += 256) {
        int k = idx >> 6, o = idx & 63;
        float s = 0.f;
        #pragma unroll 8
        for (int j = 0; j < 64; ++j) s += ib[j] * gw[(k * 64 + j) * 64 + o];
        vv[idx] = s;
    }
}

__global__ void rowsums(const float* __restrict__ cheb, float* __restrict__ rs) {
    __shared__ float sm[2][8];
    int n = blockIdx.x, tid = threadIdx.x;
    const float* p1 = cheb + 4194304UL + (size_t)n * NN;
    const float* p2 = cheb + 8388608UL + (size_t)n * NN;
    float s1 = 0.f, s2 = 0.f;
    for (int m = tid; m < NN; m += 256) { s1 += p1[m]; s2 += p2[m]; }
    #pragma unroll
    for (int off = 16; off; off >>= 1) {
        s1 += __shfl_down_sync(0xFFFFFFFFu, s1, off);
        s2 += __shfl_down_sync(0xFFFFFFFFu, s2, off);
    }
    if ((tid & 31) == 0) { sm[0][tid >> 5] = s1; sm[1][tid >> 5] = s2; }
    __syncthreads();
    if (tid == 0) {
        float a = 0.f, b = 0.f;
        #pragma unroll
        for (int w = 0; w < 8; ++w) { a += sm[0][w]; b += sm[1][w]; }
        rs[n] = a; rs[NN + n] = b;
    }
}

// ---------------------------------------------------------------------------
template <int MODE>
__global__ __launch_bounds__(256) void combine(
    const float* __restrict__ S0, const float* __restrict__ S1, const float* __restrict__ S2,
    const float* __restrict__ W, const float* __restrict__ bias,
    const float* __restrict__ gb, const float* __restrict__ rs,
    float* __restrict__ out)
{
    __shared__ float xg[64][97];
    __shared__ float bv[64];
    const int n = blockIdx.x, tid = threadIdx.x;

    for (int idx = tid; idx < 2048; idx += 256) {
        int b = idx >> 5, i = idx & 31;
        xg[b][i]      = S0[(size_t)n * 2048 + idx];
        xg[b][32 + i] = S1[(size_t)n * 2048 + idx];
        xg[b][64 + i] = S2[(size_t)n * 2048 + idx];
    }
    if (tid < 64) {
        if (MODE == 0) bv[tid] = bias[(size_t)n * 64 + tid];
        else bv[tid] = bias[tid] + rs[n] * bias[64 + tid] + rs[NN + n] * bias[128 + tid] + gb[tid];
    }
    __syncthreads();

    const float* Wn = (MODE == 0) ? (W + (size_t)n * 6144) : W;
    const int b0 = (tid >> 4) * 4;
    const int o0 = (tid & 15) * 4;
    float acc[4][4];
    #pragma unroll
    for (int i = 0; i < 4; ++i)
        #pragma unroll
        for (int j = 0; j < 4; ++j) acc[i][j] = 0.f;

    #pragma unroll 4
    for (int ki = 0; ki < 96; ++ki) {
        float4 w = *reinterpret_cast<const float4*>(Wn + ki * 64 + o0);
        float a0 = xg[b0][ki], a1 = xg[b0 + 1][ki], a2 = xg[b0 + 2][ki], a3 = xg[b0 + 3][ki];
        acc[0][0] += a0 * w.x; acc[0][1] += a0 * w.y; acc[0][2] += a0 * w.z; acc[0][3] += a0 * w.w;
        acc[1][0] += a1 * w.x; acc[1][1] += a1 * w.y; acc[1][2] += a1 * w.z; acc[1][3] += a1 * w.w;
        acc[2][0] += a2 * w.x; acc[2][1] += a2 * w.y; acc[2][2] += a2 * w.z; acc[2][3] += a2 * w.w;
        acc[3][0] += a3 * w.x; acc[3][1] += a3 * w.y; acc[3][2] += a3 * w.z; acc[3][3] += a3 * w.w;
    }
    #pragma unroll
    for (int bi = 0; bi < 4; ++bi) {
        float4 v;
        float t0 = acc[bi][0] + bv[o0 + 0];
        float t1 = acc[bi][1] + bv[o0 + 1];
        float t2 = acc[bi][2] + bv[o0 + 2];
        float t3 = acc[bi][3] + bv[o0 + 3];
        v.x = t0 >= 0.f ? t0 : 0.01f * t0;
        v.y = t1 >= 0.f ? t1 : 0.01f * t1;
        v.z = t2 >= 0.f ? t2 : 0.01f * t2;
        v.w = t3 >= 0.f ? t3 : 0.01f * t3;
        *reinterpret_cast<float4*>(out + (size_t)n * 4096 + (b0 + bi) * 64 + o0) = v;
    }
}

// ---------------------------------------------------------------------------
__global__ void colsum(const float* __restrict__ src, float* __restrict__ part) {
    int c = blockIdx.x * 256 + threadIdx.x;
    int n0 = blockIdx.y * 128;
    float s = 0.f;
    #pragma unroll 4
    for (int n = 0; n < 128; ++n) s += src[(size_t)(n0 + n) * 4096 + c];
    part[(size_t)blockIdx.y * 4096 + c] = s;
}
__global__ void colsum_fin(const float* __restrict__ part, float* __restrict__ mean) {
    int c = blockIdx.x * 256 + threadIdx.x;
    float s = 0.f;
    #pragma unroll
    for (int p = 0; p < 16; ++p) s += part[(size_t)p * 4096 + c];
    mean[c] = s * (1.0f / 2048.0f);
}

__global__ void selfatt(const float* __restrict__ w11, const float* __restrict__ w12,
                        const float* __restrict__ w21, const float* __restrict__ w22,
                        const float* __restrict__ mean, float* __restrict__ sv)
{
    int b = threadIdx.x;
    if (b >= 64) return;
    {
        float h[4] = {0.f, 0.f, 0.f, 0.f};
        for (int c = 0; c < 64; ++c) {
            float m = mean[b * 64 + c];
            #pragma unroll
            for (int r = 0; r < 4; ++r) h[r] += m * w11[c * 4 + r];
        }
        float s = 0.f;
        #pragma unroll
        for (int r = 0; r < 4; ++r) s += fmaxf(h[r], 0.f) * w12[r];
        sv[b] = fminf(fmaxf(s * (1.0f / 6.0f) + 0.5f, 0.f), 1.f);
    }
    {
        float h[4] = {0.f, 0.f, 0.f, 0.f};
        for (int c = 0; c < 64; ++c) {
            float m = mean[4096 + b * 64 + c];
            #pragma unroll
            for (int r = 0; r < 4; ++r) h[r] += m * w21[c * 4 + r];
        }
        float s = 0.f;
        #pragma unroll
        for (int r = 0; r < 4; ++r) s += fmaxf(h[r], 0.f) * w22[r];
        sv[64 + b] = fminf(fmaxf(s * (1.0f / 6.0f) + 0.5f, 0.f), 1.f);
    }
}

__global__ void finalize(const float* __restrict__ a0, const float* __restrict__ a1,
                         const float* __restrict__ sv, float* __restrict__ out)
{
    int t = blockIdx.x * 256 + threadIdx.x;
    int b = (t >> 4) & 63;
    int n = t >> 10;
    int o4 = (t & 15) << 2;
    float4 v0 = *(reinterpret_cast<const float4*>(a0) + t);
    float4 v1 = *(reinterpret_cast<const float4*>(a1) + t);
    float f0 = sv[b], f1 = sv[64 + b];
    float4 r;
    r.x = v0.x * f0 + v1.x * f1;
    r.y = v0.y * f0 + v1.y * f1;
    r.z = v0.z * f0 + v1.z * f1;
    r.w = v0.w * f0 + v1.w * f1;
    *reinterpret_cast<float4*>(out + ((size_t)b * NN + n) * 64 + o4) = r;
}

// ---------------------------------------------------------------------------
extern "C" void kernel_launch(void* const* d_in, const int* in_sizes, int n_in,
                              void* d_out, int out_size)
{
    (void)in_sizes; (void)n_in; (void)out_size;
    const float* x    = (const float*)d_in[0];
    const float* E    = (const float*)d_in[1];
    const float* L    = (const float*)d_in[2];
    const float* cheb = (const float*)d_in[3];
    const float* Wp   = (const float*)d_in[4];
    const float* Bp   = (const float*)d_in[5];
    const float* iw   = (const float*)d_in[6];
    const float* ib   = (const float*)d_in[7];
    const float* gw   = (const float*)d_in[8];
    const float* gb   = (const float*)d_in[9];
    const float* w11  = (const float*)d_in[10];
    const float* w12  = (const float*)d_in[11];
    const float* w21  = (const float*)d_in[12];
    const float* w22  = (const float*)d_in[13];
    float* out = (float*)d_out;

    float* S = nullptr;
    cudaGetSymbolAddress((void**)&S, g_scratch);
    __nv_bfloat16* BF = nullptr;
    cudaGetSymbolAddress((void**)&BF, g_bf);

    const int dyn_smem = 3 * ST_BYTES;   // 147456
    cudaFuncSetAttribute(gemm_mma<0>, cudaFuncAttributeMaxDynamicSharedMemorySize, dyn_smem);
    cudaFuncSetAttribute(gemm_mma<2>, cudaFuncAttributeMaxDynamicSharedMemorySize, dyn_smem);

    uint4* LAh = (uint4*)(BF + BF_LH);  uint4* LAl = (uint4*)(BF + BF_LL);
    uint4* C1h = (uint4*)(BF + BF_C1H); uint4* C1l = (uint4*)(BF + BF_C1L);
    uint4* C2h = (uint4*)(BF + BF_C2H); uint4* C2l = (uint4*)(BF + BF_C2L);
    uint4* XTh = (uint4*)(BF + BF_XTH); uint4* XTl = (uint4*)(BF + BF_XTL);
    uint4* YTh = (uint4*)(BF + BF_YTH); uint4* YTl = (uint4*)(BF + BF_YTL);

    pack_x<<<4096, 256>>>(x, S + OFF_XP);
    convA_frag<<<dim3(32, 32), 256>>>(L, LAh, LAl);
    convA_frag<<<dim3(32, 32), 256>>>(cheb + 4194304UL, C1h, C1l);
    convA_frag<<<dim3(32, 32), 256>>>(cheb + 8388608UL, C2h, C2l);
    convX_frag<<<dim3(32, 32), 256>>>(x, XTh, XTl);

    dim3 gg(8, 16);
    // Y1 = L @ Xp
    gemm_mma<0><<<gg, 256, dyn_smem>>>(LAh, LAl, XTh, XTl, S + OFF_Y1, nullptr);
    // Y1 -> B-fragment form for GEMM2
    convB_frag<<<dim3(32, 32), 256>>>(S + OFF_Y1, YTh, YTl);
    // G2 = 2*L @ Y1 - Xp
    gemm_mma<2><<<gg, 256, dyn_smem>>>(LAh, LAl, YTh, YTl, S + OFF_G2, S + OFF_XP);
    // U1 = cheb1 @ Xp ; U2 = cheb2 @ Xp
    gemm_mma<0><<<gg, 256, dyn_smem>>>(C1h, C1l, XTh, XTl, S + OFF_U1, nullptr);
    gemm_mma<0><<<gg, 256, dyn_smem>>>(C2h, C2l, XTh, XTl, S + OFF_U2, nullptr);

    wgen<<<dim3(48, 16), 256>>>(E, Wp, S + OFF_WALL);
    bgen<<<512, 256>>>(E, Bp, S + OFF_BALL);
    prestat<<<1, 256>>>(iw, ib, gw, S + OFF_MCAT, S + OFF_VV);
    rowsums<<<2048, 256>>>(cheb, S + OFF_RS);

    combine<0><<<2048, 256>>>(S + OFF_XP, S + OFF_Y1, S + OFF_G2,
                              S + OFF_WALL, S + OFF_BALL, nullptr, nullptr, S + OFF_A0);
    combine<1><<<2048, 256>>>(S + OFF_XP, S + OFF_U1, S + OFF_U2,
                              S + OFF_MCAT, S + OFF_VV, gb, S + OFF_RS, S + OFF_A1);

    colsum<<<dim3(16, 16), 256>>>(S + OFF_A0, S + OFF_PART);
    colsum_fin<<<16, 256>>>(S + OFF_PART, S + OFF_MEAN);
    colsum<<<dim3(16, 16), 256>>>(S + OFF_A1, S + OFF_PART);
    colsum_fin<<<16, 256>>>(S + OFF_PART, S + OFF_MEAN + 4096);

    selfatt<<<1, 64>>>(w11, w12, w21, w22, S + OFF_MEAN, S + OFF_SV);

    finalize<<<8192, 256>>>(S + OFF_A0, S + OFF_A1, S + OFF_SV, out);
}

// round 5
// speedup vs baseline: 2.3408x; 1.0297x over previous
#include <cuda_runtime.h>
#include <cuda_bf16.h>
#include <cstdint>

// Problem constants: B=64, N=2048, CI=32, CO=64, K=3, D=16, RED=16
#define NN 2048
#define BB 64
#define CI 32
#define CO 64
#define DD 16

// ---------------------------------------------------------------------------
// fp32 scratch
#define OFF_XP    0UL
#define OFF_Y1    4194304UL
#define OFF_G2    8388608UL
#define OFF_U1    12582912UL
#define OFF_U2    16777216UL
#define OFF_WALL  20971520UL
#define OFF_BALL  33554432UL
#define OFF_MCAT  33685504UL
#define OFF_VV    33691648UL
#define OFF_RS    33691840UL
#define OFF_A0    33695936UL
#define OFF_A1    42084544UL
#define OFF_PART  50473152UL                // [32][4096] (A0: 0..15, A1: 16..31)
#define OFF_MEAN  50604224UL                // [2][4096]
#define OFF_SV    50612416UL                // [2][64]
#define SCRATCH_FLOATS 50612544UL

__device__ float g_scratch[SCRATCH_FLOATS];

// bf16 fragment-layout operand arrays (each 2048x2048 = 4194304 bf16 = 8MB)
#define BF_LH   0UL
#define BF_LL   4194304UL
#define BF_C1H  8388608UL
#define BF_C1L  12582912UL
#define BF_UTH  16777216UL
#define BF_UTL  20971520UL
#define BF_XTH  25165824UL
#define BF_XTL  29360128UL
#define BF_YTH  33554432UL
#define BF_YTL  37748736UL
#define BF_TOTAL 41943040UL

__device__ __align__(1024) __nv_bfloat16 g_bf[BF_TOTAL];

// ---------------------------------------------------------------------------
__device__ __forceinline__ uint32_t smem_u32(const void* p) {
    uint32_t a;
    asm("{ .reg .u64 t; cvta.to.shared.u64 t, %1; cvt.u32.u64 %0, t; }" : "=r"(a) : "l"(p));
    return a;
}
__device__ __forceinline__ void cp16(uint32_t s, const void* g) {
    asm volatile("cp.async.cg.shared.global [%0], [%1], 16;" :: "r"(s), "l"(g));
}
__device__ __forceinline__ uint4 lds128(uint32_t a) {
    uint4 v;
    asm volatile("ld.shared.v4.b32 {%0,%1,%2,%3}, [%4];"
                 : "=r"(v.x), "=r"(v.y), "=r"(v.z), "=r"(v.w) : "r"(a));
    return v;
}
__device__ __forceinline__ void mma16816(float* d, const uint4& a, uint32_t b0, uint32_t b1) {
    asm volatile(
        "mma.sync.aligned.m16n8k16.row.col.f32.bf16.bf16.f32 "
        "{%0,%1,%2,%3},{%4,%5,%6,%7},{%8,%9},{%0,%1,%2,%3};"
        : "+f"(d[0]), "+f"(d[1]), "+f"(d[2]), "+f"(d[3])
        : "r"(a.x), "r"(a.y), "r"(a.z), "r"(a.w), "r"(b0), "r"(b1));
}
__device__ __forceinline__ uint32_t pack_bf2(float v0, float v1) {
    __nv_bfloat162 p;
    p.x = __float2bfloat16(v0);
    p.y = __float2bfloat16(v1);
    return *reinterpret_cast<uint32_t*>(&p);
}

// ---------------------------------------------------------------------------
// Pack x[b][m][c] -> Xp[m][b*32+c]  (fp32 natural)
__global__ void pack_x(const float* __restrict__ x, float* __restrict__ Xp) {
    int t = blockIdx.x * 256 + threadIdx.x;
    int c4 = (t & 7) * 4;
    int m  = (t >> 3) & 2047;
    int b  = t >> 14;
    float4 v = *reinterpret_cast<const float4*>(x + ((size_t)b * NN + m) * CI + c4);
    *reinterpret_cast<float4*>(Xp + (size_t)m * (BB * CI) + b * CI + c4) = v;
}

// ---------------------------------------------------------------------------
// A-fragment conversion: natural fp32 [row m][col k] -> Ah/Al frag arrays.
__global__ __launch_bounds__(256) void convA_frag(const float* __restrict__ src,
                                                  uint4* __restrict__ Ah,
                                                  uint4* __restrict__ Al)
{
    __shared__ float sm[64][65];
    const int bx = blockIdx.x, by = blockIdx.y;   // k-region, m-region
    const int tid = threadIdx.x;
    const float* s0 = src + (size_t)(by * 64) * 2048 + bx * 64;
    #pragma unroll
    for (int i = 0; i < 4; ++i) {
        int idx = tid + i * 256;
        int r = idx >> 4, c4 = (idx & 15) * 4;
        float4 v = *reinterpret_cast<const float4*>(s0 + (size_t)r * 2048 + c4);
        sm[r][c4] = v.x; sm[r][c4 + 1] = v.y; sm[r][c4 + 2] = v.z; sm[r][c4 + 3] = v.w;
    }
    __syncthreads();
    const int w = tid >> 5, lane = tid & 31, g = lane >> 2, t = lane & 3;
    #pragma unroll
    for (int rep = 0; rep < 2; ++rep) {
        int id = w * 2 + rep;
        int mt_l = id >> 2, kt_l = id & 3;
        uint32_t hw[4], lw[4];
        #pragma unroll
        for (int wd = 0; wd < 4; ++wd) {
            int khi = wd >> 1, hi8 = wd & 1;
            int m = mt_l * 16 + hi8 * 8 + g;
            int k = kt_l * 16 + khi * 8 + t * 2;
            float v0 = sm[m][k], v1 = sm[m][k + 1];
            __nv_bfloat16 h0 = __float2bfloat16(v0), h1 = __float2bfloat16(v1);
            hw[wd] = pack_bf2(v0, v1);
            lw[wd] = pack_bf2(v0 - __bfloat162float(h0), v1 - __bfloat162float(h1));
        }
        size_t fi = (((size_t)by * 4 + mt_l) * 128 + (bx * 4 + kt_l)) * 32 + lane;
        Ah[fi] = make_uint4(hw[0], hw[1], hw[2], hw[3]);
        Al[fi] = make_uint4(lw[0], lw[1], lw[2], lw[3]);
    }
}

// B-fragment conversion directly from x[b][m][ci]: B-row j = b*32+ci, K = m.
__global__ __launch_bounds__(256) void convX_frag(const float* __restrict__ x,
                                                  uint4* __restrict__ Bh,
                                                  uint4* __restrict__ Bl)
{
    __shared__ float sm[64][65];
    const int bx = blockIdx.x, by = blockIdx.y;   // j-region (2 b's), m-region
    const int tid = threadIdx.x;
    for (int i = 0; i < 16; ++i) {
        int idx = tid + i * 256;
        int b_l = idx >> 11, m_l = (idx >> 5) & 63, ci = idx & 31;
        sm[m_l][b_l * 32 + ci] =
            x[((size_t)(bx * 2 + b_l) * 2048 + by * 64 + m_l) * 32 + ci];
    }
    __syncthreads();
    const int w = tid >> 5, lane = tid & 31, g = lane >> 2, t = lane & 3;
    #pragma unroll
    for (int rep = 0; rep < 2; ++rep) {
        int id = w * 2 + rep;
        int ntp_l = id >> 2, kt_l = id & 3;
        uint32_t hw[4], lw[4];
        #pragma unroll
        for (int wd = 0; wd < 4; ++wd) {
            int nt_odd = wd >> 1, khi = wd & 1;
            int j = ntp_l * 16 + nt_odd * 8 + g;
            int m = kt_l * 16 + khi * 8 + t * 2;
            float v0 = sm[m][j], v1 = sm[m + 1][j];
            __nv_bfloat16 h0 = __float2bfloat16(v0), h1 = __float2bfloat16(v1);
            hw[wd] = pack_bf2(v0, v1);
            lw[wd] = pack_bf2(v0 - __bfloat162float(h0), v1 - __bfloat162float(h1));
        }
        size_t fi = (((size_t)bx * 4 + ntp_l) * 128 + (by * 4 + kt_l)) * 32 + lane;
        Bh[fi] = make_uint4(hw[0], hw[1], hw[2], hw[3]);
        Bl[fi] = make_uint4(lw[0], lw[1], lw[2], lw[3]);
    }
}

// ---------------------------------------------------------------------------
// bf16-split tensor-core GEMM: C[2048,2048] = A @ Bt^T (fp32 out)
// acc = Ah*Bh + Ah*Bl + Al*Bh.  CTA 128(M)x256(N), warp 64x64, BK=32, 4-stage.
// MODE 1: C = acc; also emit B-fragments (hi/lo) of C for next GEMM.
// MODE 2: C = 2*acc - Xp.
#define ST_BYTES 49152
#define NSTAGE 4

template <int MODE>
__global__ __launch_bounds__(256, 1) void gemm_mma(
    const uint4* __restrict__ Ah, const uint4* __restrict__ Al,
    const uint4* __restrict__ Bh, const uint4* __restrict__ Bl,
    float* __restrict__ C, const float* __restrict__ Xp,
    uint4* __restrict__ Fh, uint4* __restrict__ Fl)
{
    extern __shared__ char smem[];
    const int tid = threadIdx.x, lane = tid & 31, wid = tid >> 5;
    const int wm = wid >> 2, wn = wid & 3;
    const int g = lane >> 2, t = lane & 3;
    const int bn = blockIdx.x, bm = blockIdx.y;
    const uint32_t sb = smem_u32(smem);

    float acc[4][8][4];
    #pragma unroll
    for (int i = 0; i < 4; ++i)
        #pragma unroll
        for (int j = 0; j < 8; ++j)
            #pragma unroll
            for (int q = 0; q < 4; ++q) acc[i][j][q] = 0.f;

    auto issue = [&](int c) {
        uint32_t SB = sb + (c & 3) * ST_BYTES;
        #pragma unroll
        for (int r2 = 0; r2 < 2; ++r2) {
            int q = tid + r2 * 256;
            int u = q >> 5, ln = q & 31;
            size_t gi = (((size_t)bm * 8 + (u >> 1)) * 128 + (c * 2 + (u & 1))) * 32 + ln;
            cp16(SB + q * 16, Ah + gi);
            cp16(SB + 8192 + q * 16, Al + gi);
        }
        #pragma unroll
        for (int r2 = 0; r2 < 4; ++r2) {
            int q = tid + r2 * 256;
            int u = q >> 5, ln = q & 31;
            size_t gi = (((size_t)bn * 16 + (u >> 1)) * 128 + (c * 2 + (u & 1))) * 32 + ln;
            cp16(SB + 16384 + q * 16, Bh + gi);
            cp16(SB + 32768 + q * 16, Bl + gi);
        }
    };

    issue(0); asm volatile("cp.async.commit_group;" ::: "memory");
    issue(1); asm volatile("cp.async.commit_group;" ::: "memory");
    issue(2); asm volatile("cp.async.commit_group;" ::: "memory");

    for (int c = 0; c < 64; ++c) {
        asm volatile("cp.async.wait_group 2;" ::: "memory");
        __syncthreads();
        if (c + 3 < 64) issue(c + 3);
        asm volatile("cp.async.commit_group;" ::: "memory");

        const uint32_t SB = sb + (c & 3) * ST_BYTES;
        #pragma unroll
        for (int ktl = 0; ktl < 2; ++ktl) {
            uint4 ah[4], bh[4];
            #pragma unroll
            for (int mt = 0; mt < 4; ++mt)
                ah[mt] = lds128(SB + ((wm * 4 + mt) * 2 + ktl) * 512 + lane * 16);
            #pragma unroll
            for (int np = 0; np < 4; ++np)
                bh[np] = lds128(SB + 16384 + ((wn * 4 + np) * 2 + ktl) * 512 + lane * 16);
            #pragma unroll
            for (int mt = 0; mt < 4; ++mt)
                #pragma unroll
                for (int np = 0; np < 4; ++np) {
                    mma16816(acc[mt][np * 2],     ah[mt], bh[np].x, bh[np].y);
                    mma16816(acc[mt][np * 2 + 1], ah[mt], bh[np].z, bh[np].w);
                }
            uint4 bl[4];
            #pragma unroll
            for (int np = 0; np < 4; ++np)
                bl[np] = lds128(SB + 32768 + ((wn * 4 + np) * 2 + ktl) * 512 + lane * 16);
            #pragma unroll
            for (int mt = 0; mt < 4; ++mt)
                #pragma unroll
                for (int np = 0; np < 4; ++np) {
                    mma16816(acc[mt][np * 2],     ah[mt], bl[np].x, bl[np].y);
                    mma16816(acc[mt][np * 2 + 1], ah[mt], bl[np].z, bl[np].w);
                }
            uint4 al[4];
            #pragma unroll
            for (int mt = 0; mt < 4; ++mt)
                al[mt] = lds128(SB + 8192 + ((wm * 4 + mt) * 2 + ktl) * 512 + lane * 16);
            #pragma unroll
            for (int mt = 0; mt < 4; ++mt)
                #pragma unroll
                for (int np = 0; np < 4; ++np) {
                    mma16816(acc[mt][np * 2],     al[mt], bh[np].x, bh[np].y);
                    mma16816(acc[mt][np * 2 + 1], al[mt], bh[np].z, bh[np].w);
                }
        }
    }

    // ---- epilogue: stage warp's 64x64 fp32 tile in smem, then write ----
    asm volatile("cp.async.wait_group 0;" ::: "memory");
    __syncthreads();
    float* tw = reinterpret_cast<float*>(smem) + wid * (64 * 68);
    #pragma unroll
    for (int mt = 0; mt < 4; ++mt)
        #pragma unroll
        for (int nt = 0; nt < 8; ++nt) {
            int r = mt * 16 + g, cc = nt * 8 + t * 2;
            float* a = acc[mt][nt];
            tw[r * 68 + cc] = a[0];       tw[r * 68 + cc + 1] = a[1];
            tw[(r + 8) * 68 + cc] = a[2]; tw[(r + 8) * 68 + cc + 1] = a[3];
        }
    __syncwarp();

    const int row0g = bm * 128 + wm * 64;
    const int col0g = bn * 256 + wn * 64;

    #pragma unroll 4
    for (int rr = 0; rr < 32; ++rr) {
        int row = rr * 2 + (lane >> 4);
        int c4 = (lane & 15) * 4;
        float v0 = tw[row * 68 + c4],     v1 = tw[row * 68 + c4 + 1];
        float v2 = tw[row * 68 + c4 + 2], v3 = tw[row * 68 + c4 + 3];
        size_t gi = (size_t)(row0g + row) * 2048 + col0g + c4;
        if (MODE == 2) {
            float4 xp = *reinterpret_cast<const float4*>(Xp + gi);
            v0 = 2.f * v0 - xp.x; v1 = 2.f * v1 - xp.y;
            v2 = 2.f * v2 - xp.z; v3 = 2.f * v3 - xp.w;
        }
        *reinterpret_cast<float4*>(C + gi) = make_float4(v0, v1, v2, v3);
    }

    if (MODE == 1) {
        #pragma unroll
        for (int ntp_l = 0; ntp_l < 4; ++ntp_l)
            #pragma unroll
            for (int kt_l = 0; kt_l < 4; ++kt_l) {
                uint32_t hw[4], lw[4];
                #pragma unroll
                for (int wd = 0; wd < 4; ++wd) {
                    int nt_odd = wd >> 1, khi = wd & 1;
                    int jl = ntp_l * 16 + nt_odd * 8 + g;
                    int nl = kt_l * 16 + khi * 8 + t * 2;
                    float v0 = tw[nl * 68 + jl];
                    float v1 = tw[(nl + 1) * 68 + jl];
                    __nv_bfloat16 h0 = __float2bfloat16(v0), h1 = __float2bfloat16(v1);
                    hw[wd] = pack_bf2(v0, v1);
                    lw[wd] = pack_bf2(v0 - __bfloat162float(h0), v1 - __bfloat162float(h1));
                }
                size_t fi = (((size_t)(col0g >> 4) + ntp_l) * 128 + ((row0g >> 4) + kt_l)) * 32 + lane;
                Fh[fi] = make_uint4(hw[0], hw[1], hw[2], hw[3]);
                Fl[fi] = make_uint4(lw[0], lw[1], lw[2], lw[3]);
            }
    }
}

// ---------------------------------------------------------------------------
// Wall[n][ki][o] = sum_d E[n][d] * Wp[d][ki][o]
__global__ __launch_bounds__(256) void wgen(
    const float* __restrict__ E, const float* __restrict__ Wp, float* __restrict__ Wall)
{
    __shared__ float Es[128][17];
    __shared__ float Bs[16][128];
    const int cb = blockIdx.x, nb = blockIdx.y;
    const int tid = threadIdx.x;
    #pragma unroll
    for (int r = 0; r < 2; ++r) {
        int la = tid + r * 256;
        int row = la >> 2, c4 = (la & 3) * 4;
        float4 v = *reinterpret_cast<const float4*>(E + (size_t)(nb * 128 + row) * DD + c4);
        Es[row][c4] = v.x; Es[row][c4 + 1] = v.y; Es[row][c4 + 2] = v.z; Es[row][c4 + 3] = v.w;
        int kr = la >> 5, n4 = (la & 31) * 4;
        *reinterpret_cast<float4*>(&Bs[kr][n4]) =
            *reinterpret_cast<const float4*>(Wp + (size_t)kr * 6144 + cb * 128 + n4);
    }
    __syncthreads();
    const int tx = tid & 15, ty = tid >> 4;
    float acc[8][8];
    #pragma unroll
    for (int i = 0; i < 8; ++i)
        #pragma unroll
        for (int j = 0; j < 8; ++j) acc[i][j] = 0.f;
    #pragma unroll
    for (int k = 0; k < 16; ++k) {
        float ar[8], br[8];
        #pragma unroll
        for (int i = 0; i < 8; ++i) ar[i] = Es[ty * 8 + i][k];
        #pragma unroll
        for (int j = 0; j < 8; ++j) br[j] = Bs[k][tx * 8 + j];
        #pragma unroll
        for (int i = 0; i < 8; ++i)
            #pragma unroll
            for (int j = 0; j < 8; ++j) acc[i][j] += ar[i] * br[j];
    }
    #pragma unroll
    for (int i = 0; i < 8; ++i) {
        size_t idx = (size_t)(nb * 128 + ty * 8 + i) * 6144 + cb * 128 + tx * 8;
        float4 v0, v1;
        v0.x = acc[i][0]; v0.y = acc[i][1]; v0.z = acc[i][2]; v0.w = acc[i][3];
        v1.x = acc[i][4]; v1.y = acc[i][5]; v1.z = acc[i][6]; v1.w = acc[i][7];
        *reinterpret_cast<float4*>(Wall + idx) = v0;
        *reinterpret_cast<float4*>(Wall + idx + 4) = v1;
    }
}

__global__ void bgen(const float* __restrict__ E, const float* __restrict__ Bp,
                     float* __restrict__ Ball)
{
    int t = blockIdx.x * 256 + threadIdx.x;
    int n = t >> 6, o = t & 63;
    float s = 0.f;
    #pragma unroll
    for (int d = 0; d < DD; ++d) s += E[n * DD + d] * Bp[d * CO + o];
    Ball[t] = s;
}

__global__ void prestat(const float* __restrict__ iw, const float* __restrict__ ib,
                        const float* __restrict__ gw, float* __restrict__ Mcat,
                        float* __restrict__ vv)
{
    int tid = threadIdx.x;
    for (int idx = tid; idx < 96 * 64; idx += 256) {
        int ki = idx >> 6, o = idx & 63;
        int k = ki >> 5, i = ki & 31;
        float s = 0.f;
        #pragma unroll 8
        for (int j = 0; j < 64; ++j) s += iw[i * 64 + j] * gw[(k * 64 + j) * 64 + o];
        Mcat[idx] = s;
    }
    for (int idx = tid; idx < 192; idx += 256) {
        int k = idx >> 6, o = idx & 63;
        float s = 0.f;
        #pragma unroll 8
        for (int j = 0; j < 64; ++j) s += ib[j] * gw[(k * 64 + j) * 64 + o];
        vv[idx] = s;
    }
}

__global__ void rowsums(const float* __restrict__ cheb, float* __restrict__ rs) {
    __shared__ float sm[2][8];
    int n = blockIdx.x, tid = threadIdx.x;
    const float* p1 = cheb + 4194304UL + (size_t)n * NN;
    const float* p2 = cheb + 8388608UL + (size_t)n * NN;
    float s1 = 0.f, s2 = 0.f;
    for (int m = tid; m < NN; m += 256) { s1 += p1[m]; s2 += p2[m]; }
    #pragma unroll
    for (int off = 16; off; off >>= 1) {
        s1 += __shfl_down_sync(0xFFFFFFFFu, s1, off);
        s2 += __shfl_down_sync(0xFFFFFFFFu, s2, off);
    }
    if ((tid & 31) == 0) { sm[0][tid >> 5] = s1; sm[1][tid >> 5] = s2; }
    __syncthreads();
    if (tid == 0) {
        float a = 0.f, b = 0.f;
        #pragma unroll
        for (int w = 0; w < 8; ++w) { a += sm[0][w]; b += sm[1][w]; }
        rs[n] = a; rs[NN + n] = b;
    }
}

// ---------------------------------------------------------------------------
template <int MODE>
__global__ __launch_bounds__(256) void combine(
    const float* __restrict__ S0, const float* __restrict__ S1, const float* __restrict__ S2,
    const float* __restrict__ W, const float* __restrict__ bias,
    const float* __restrict__ gb, const float* __restrict__ rs,
    float* __restrict__ out)
{
    __shared__ float xg[64][97];
    __shared__ float bv[64];
    const int n = blockIdx.x, tid = threadIdx.x;

    for (int idx = tid; idx < 2048; idx += 256) {
        int b = idx >> 5, i = idx & 31;
        xg[b][i]      = S0[(size_t)n * 2048 + idx];
        xg[b][32 + i] = S1[(size_t)n * 2048 + idx];
        xg[b][64 + i] = S2[(size_t)n * 2048 + idx];
    }
    if (tid < 64) {
        if (MODE == 0) bv[tid] = bias[(size_t)n * 64 + tid];
        else bv[tid] = bias[tid] + rs[n] * bias[64 + tid] + rs[NN + n] * bias[128 + tid] + gb[tid];
    }
    __syncthreads();

    const float* Wn = (MODE == 0) ? (W + (size_t)n * 6144) : W;
    const int b0 = (tid >> 4) * 4;
    const int o0 = (tid & 15) * 4;
    float acc[4][4];
    #pragma unroll
    for (int i = 0; i < 4; ++i)
        #pragma unroll
        for (int j = 0; j < 4; ++j) acc[i][j] = 0.f;

    #pragma unroll 4
    for (int ki = 0; ki < 96; ++ki) {
        float4 w = *reinterpret_cast<const float4*>(Wn + ki * 64 + o0);
        float a0 = xg[b0][ki], a1 = xg[b0 + 1][ki], a2 = xg[b0 + 2][ki], a3 = xg[b0 + 3][ki];
        acc[0][0] += a0 * w.x; acc[0][1] += a0 * w.y; acc[0][2] += a0 * w.z; acc[0][3] += a0 * w.w;
        acc[1][0] += a1 * w.x; acc[1][1] += a1 * w.y; acc[1][2] += a1 * w.z; acc[1][3] += a1 * w.w;
        acc[2][0] += a2 * w.x; acc[2][1] += a2 * w.y; acc[2][2] += a2 * w.z; acc[2][3] += a2 * w.w;
        acc[3][0] += a3 * w.x; acc[3][1] += a3 * w.y; acc[3][2] += a3 * w.z; acc[3][3] += a3 * w.w;
    }
    #pragma unroll
    for (int bi = 0; bi < 4; ++bi) {
        float4 v;
        float t0 = acc[bi][0] + bv[o0 + 0];
        float t1 = acc[bi][1] + bv[o0 + 1];
        float t2 = acc[bi][2] + bv[o0 + 2];
        float t3 = acc[bi][3] + bv[o0 + 3];
        v.x = t0 >= 0.f ? t0 : 0.01f * t0;
        v.y = t1 >= 0.f ? t1 : 0.01f * t1;
        v.z = t2 >= 0.f ? t2 : 0.01f * t2;
        v.w = t3 >= 0.f ? t3 : 0.01f * t3;
        *reinterpret_cast<float4*>(out + (size_t)n * 4096 + (b0 + bi) * 64 + o0) = v;
    }
}

// ---------------------------------------------------------------------------
// Column sums over n for BOTH A0 and A1 in one launch
__global__ void colsum2(const float* __restrict__ a0, const float* __restrict__ a1,
                        float* __restrict__ part) {
    int c = blockIdx.x * 256 + threadIdx.x;
    int n0 = blockIdx.y * 128;
    float s0 = 0.f, s1 = 0.f;
    #pragma unroll 4
    for (int n = 0; n < 128; ++n) {
        s0 += a0[(size_t)(n0 + n) * 4096 + c];
        s1 += a1[(size_t)(n0 + n) * 4096 + c];
    }
    part[(size_t)blockIdx.y * 4096 + c] = s0;
    part[(size_t)(blockIdx.y + 16) * 4096 + c] = s1;
}
__global__ void colsum_fin2(const float* __restrict__ part, float* __restrict__ mean) {
    int c = blockIdx.x * 256 + threadIdx.x;     // 32 blocks: 0..15 A0, 16..31 A1
    int half = c >> 12;
    int cc = c & 4095;
    float s = 0.f;
    #pragma unroll
    for (int p = 0; p < 16; ++p) s += part[(size_t)(half * 16 + p) * 4096 + cc];
    mean[(size_t)half * 4096 + cc] = s * (1.0f / 2048.0f);
}

__global__ void selfatt(const float* __restrict__ w11, const float* __restrict__ w12,
                        const float* __restrict__ w21, const float* __restrict__ w22,
                        const float* __restrict__ mean, float* __restrict__ sv)
{
    int b = threadIdx.x;
    if (b >= 64) return;
    {
        float h[4] = {0.f, 0.f, 0.f, 0.f};
        for (int c = 0; c < 64; ++c) {
            float m = mean[b * 64 + c];
            #pragma unroll
            for (int r = 0; r < 4; ++r) h[r] += m * w11[c * 4 + r];
        }
        float s = 0.f;
        #pragma unroll
        for (int r = 0; r < 4; ++r) s += fmaxf(h[r], 0.f) * w12[r];
        sv[b] = fminf(fmaxf(s * (1.0f / 6.0f) + 0.5f, 0.f), 1.f);
    }
    {
        float h[4] = {0.f, 0.f, 0.f, 0.f};
        for (int c = 0; c < 64; ++c) {
            float m = mean[4096 + b * 64 + c];
            #pragma unroll
            for (int r = 0; r < 4; ++r) h[r] += m * w21[c * 4 + r];
        }
        float s = 0.f;
        #pragma unroll
        for (int r = 0; r < 4; ++r) s += fmaxf(h[r], 0.f) * w22[r];
        sv[64 + b] = fminf(fmaxf(s * (1.0f / 6.0f) + 0.5f, 0.f), 1.f);
    }
}

__global__ void finalize(const float* __restrict__ a0, const float* __restrict__ a1,
                         const float* __restrict__ sv, float* __restrict__ out)
{
    int t = blockIdx.x * 256 + threadIdx.x;
    int b = (t >> 4) & 63;
    int n = t >> 10;
    int o4 = (t & 15) << 2;
    float4 v0 = *(reinterpret_cast<const float4*>(a0) + t);
    float4 v1 = *(reinterpret_cast<const float4*>(a1) + t);
    float f0 = sv[b], f1 = sv[64 + b];
    float4 r;
    r.x = v0.x * f0 + v1.x * f1;
    r.y = v0.y * f0 + v1.y * f1;
    r.z = v0.z * f0 + v1.z * f1;
    r.w = v0.w * f0 + v1.w * f1;
    *reinterpret_cast<float4*>(out + ((size_t)b * NN + n) * 64 + o4) = r;
}

// ---------------------------------------------------------------------------
extern "C" void kernel_launch(void* const* d_in, const int* in_sizes, int n_in,
                              void* d_out, int out_size)
{
    (void)in_sizes; (void)n_in; (void)out_size;
    const float* x    = (const float*)d_in[0];
    const float* E    = (const float*)d_in[1];
    const float* L    = (const float*)d_in[2];
    const float* cheb = (const float*)d_in[3];
    const float* Wp   = (const float*)d_in[4];
    const float* Bp   = (const float*)d_in[5];
    const float* iw   = (const float*)d_in[6];
    const float* ib   = (const float*)d_in[7];
    const float* gw   = (const float*)d_in[8];
    const float* gb   = (const float*)d_in[9];
    const float* w11  = (const float*)d_in[10];
    const float* w12  = (const float*)d_in[11];
    const float* w21  = (const float*)d_in[12];
    const float* w22  = (const float*)d_in[13];
    float* out = (float*)d_out;

    float* S = nullptr;
    cudaGetSymbolAddress((void**)&S, g_scratch);
    __nv_bfloat16* BF = nullptr;
    cudaGetSymbolAddress((void**)&BF, g_bf);

    const int dyn_smem = NSTAGE * ST_BYTES;   // 196608
    cudaFuncSetAttribute(gemm_mma<1>, cudaFuncAttributeMaxDynamicSharedMemorySize, dyn_smem);
    cudaFuncSetAttribute(gemm_mma<2>, cudaFuncAttributeMaxDynamicSharedMemorySize, dyn_smem);

    uint4* LAh = (uint4*)(BF + BF_LH);  uint4* LAl = (uint4*)(BF + BF_LL);
    uint4* C1h = (uint4*)(BF + BF_C1H); uint4* C1l = (uint4*)(BF + BF_C1L);
    uint4* UTh = (uint4*)(BF + BF_UTH); uint4* UTl = (uint4*)(BF + BF_UTL);
    uint4* XTh = (uint4*)(BF + BF_XTH); uint4* XTl = (uint4*)(BF + BF_XTL);
    uint4* YTh = (uint4*)(BF + BF_YTH); uint4* YTl = (uint4*)(BF + BF_YTL);

    pack_x<<<4096, 256>>>(x, S + OFF_XP);
    convA_frag<<<dim3(32, 32), 256>>>(L, LAh, LAl);
    convA_frag<<<dim3(32, 32), 256>>>(cheb + 4194304UL, C1h, C1l);
    convX_frag<<<dim3(32, 32), 256>>>(x, XTh, XTl);

    dim3 gg(8, 16);
    // Y1 = L @ Xp (emit YT frags); G2 = 2*L @ Y1 - Xp
    gemm_mma<1><<<gg, 256, dyn_smem>>>(LAh, LAl, XTh, XTl, S + OFF_Y1, nullptr, YTh, YTl);
    gemm_mma<2><<<gg, 256, dyn_smem>>>(LAh, LAl, YTh, YTl, S + OFF_G2, S + OFF_XP, nullptr, nullptr);
    // U1 = C1 @ Xp (emit UT frags); U2 = 2*C1 @ U1 - Xp  (Chebyshev identity)
    gemm_mma<1><<<gg, 256, dyn_smem>>>(C1h, C1l, XTh, XTl, S + OFF_U1, nullptr, UTh, UTl);
    gemm_mma<2><<<gg, 256, dyn_smem>>>(C1h, C1l, UTh, UTl, S + OFF_U2, S + OFF_XP, nullptr, nullptr);

    wgen<<<dim3(48, 16), 256>>>(E, Wp, S + OFF_WALL);
    bgen<<<512, 256>>>(E, Bp, S + OFF_BALL);
    prestat<<<1, 256>>>(iw, ib, gw, S + OFF_MCAT, S + OFF_VV);
    rowsums<<<2048, 256>>>(cheb, S + OFF_RS);

    combine<0><<<2048, 256>>>(S + OFF_XP, S + OFF_Y1, S + OFF_G2,
                              S + OFF_WALL, S + OFF_BALL, nullptr, nullptr, S + OFF_A0);
    combine<1><<<2048, 256>>>(S + OFF_XP, S + OFF_U1, S + OFF_U2,
                              S + OFF_MCAT, S + OFF_VV, gb, S + OFF_RS, S + OFF_A1);

    colsum2<<<dim3(16, 16), 256>>>(S + OFF_A0, S + OFF_A1, S + OFF_PART);
    colsum_fin2<<<32, 256>>>(S + OFF_PART, S + OFF_MEAN);

    selfatt<<<1, 64>>>(w11, w12, w21, w22, S + OFF_MEAN, S + OFF_SV);

    finalize<<<8192, 256>>>(S + OFF_A0, S + OFF_A1, S + OFF_SV, out);
}